// round 1
// baseline (speedup 1.0000x reference)
#include <cuda_runtime.h>

// AutoregressiveBisectionInverter — closed-form inversion.
// W is strictly lower triangular, so the bisected scalar function is LINEAR in
// x_i:  f(xi) = softplus(a_i)*xi + sum_{j<i} W[i,j]*tanh(x_j) - y_i.
// Root: x_i = (y_i - sum_{j<i} W[i,j]*tanh(x_j)) / softplus(a_i).
// 64-step autoregressive recurrence per batch row; 512 independent rows.
//
// Layout: one warp per row. Lane l owns dims {l, l+32} (acc, y, inv_sp, out in
// registers). W staged in smem with row stride 65 -> conflict-free column reads.

#define AD 64
#define AB 512
#define ROWS_PER_BLOCK 4
#define NTHREADS (32 * ROWS_PER_BLOCK)

__global__ __launch_bounds__(NTHREADS, 8)
void arbi_kernel(const float* __restrict__ y,
                 const float* __restrict__ a,
                 const float* __restrict__ W,
                 float* __restrict__ out)
{
    __shared__ float Wsh[AD * 65];

    const int tid  = threadIdx.x;
    const int lane = tid & 31;
    const int warp = tid >> 5;
    const int row  = blockIdx.x * ROWS_PER_BLOCK + warp;

    // Stage W into padded shared memory (each block reads the full 16 KB once).
    #pragma unroll
    for (int idx = tid; idx < AD * AD; idx += NTHREADS) {
        int r = idx >> 6;
        int c = idx & 63;
        Wsh[r * 65 + c] = W[idx];
    }

    // Per-lane parameters for the two owned dims.
    const float a0 = a[lane];
    const float a1 = a[lane + 32];
    // softplus(a) = log1p(exp(a)); a in [0.5, 1.5] so no overflow concerns.
    const float inv0 = 1.0f / log1pf(__expf(a0));
    const float inv1 = 1.0f / log1pf(__expf(a1));
    const float y0 = y[row * AD + lane];
    const float y1 = y[row * AD + lane + 32];

    __syncthreads();

    float acc0 = 0.0f, acc1 = 0.0f;
    float out0 = 0.0f, out1 = 0.0f;

    #pragma unroll
    for (int i = 0; i < AD; ++i) {
        // Owner lane (i & 31) computes the root for dim i from its registers.
        float xc;
        if (i < 32) xc = (y0 - acc0) * inv0;
        else        xc = (y1 - acc1) * inv1;
        const float xb = __shfl_sync(0xffffffffu, xc, i & 31);

        // Record the solved coordinate in the owner's output register.
        if ((i & 31) == lane) {
            if (i < 32) out0 = xb;
            else        out1 = xb;
        }

        // Accurate fast tanh: tanh(x) = (e^{2x}-1)/(e^{2x}+1).
        // |x| <= ~10 here, so e^{2x} <= e^20 — no overflow.
        const float e = __expf(2.0f * xb);
        const float t = __fdividef(e - 1.0f, e + 1.0f);

        // Fan-out update: acc_k += W[k][i] * tanh(x_i). W[k][i]=0 for k<=i,
        // so updating all rows unconditionally is exact. Off critical path.
        const float w0 = Wsh[lane * 65 + i];
        const float w1 = Wsh[(lane + 32) * 65 + i];
        acc0 = fmaf(w0, t, acc0);
        acc1 = fmaf(w1, t, acc1);
    }

    // Coalesced output store.
    out[row * AD + lane]      = out0;
    out[row * AD + lane + 32] = out1;
}

extern "C" void kernel_launch(void* const* d_in, const int* in_sizes, int n_in,
                              void* d_out, int out_size)
{
    const float* y = (const float*)d_in[0];   // (512, 64)
    const float* a = (const float*)d_in[1];   // (64,)
    const float* W = (const float*)d_in[2];   // (64, 64)
    float* out = (float*)d_out;               // (512, 64)

    arbi_kernel<<<AB / ROWS_PER_BLOCK, NTHREADS>>>(y, a, W, out);
}

// round 3
// speedup vs baseline: 1.3527x; 1.3527x over previous
#include <cuda_runtime.h>

// AutoregressiveBisectionInverter — closed-form inversion, latency-optimized.
//
// W strictly lower triangular => bisected function is linear in x_i:
//   x_i = (y_i - sum_{j<i} W[i,j] tanh(x_j)) / softplus(a_i)
//
// Pre-scale: Wsh[i][j] = -W[i,j]/softplus(a_i), y'_i = y_i/softplus(a_i)
//   => x_i = y'_i + sum_{j<i} Wsh[i,j] * tanh(x_j)   (pure FMA accumulation)
//
// One warp per batch row. Lane l keeps accumulators for dims {l, l+32}.
// Dims processed in 4-dim chunks; the partial sums for the NEXT chunk are
// shfl-broadcast 2 dims early and the last two tanh-updates are replayed
// redundantly on all lanes, so the 26-cycle shfl is fully hidden and the
// steady-state critical path is FMA(4)+MUFU.TANH(16) = 20 cyc/dim.

#define AD 64
#define AB 512
#define ROWS_PER_BLOCK 4
#define NTHREADS (32 * ROWS_PER_BLOCK)

__device__ __forceinline__ float tanh_fast(float x) {
    float r;
    asm("tanh.approx.f32 %0, %1;" : "=f"(r) : "f"(x));
    return r;
}

__global__ __launch_bounds__(NTHREADS)
void arbi_kernel(const float* __restrict__ y,
                 const float* __restrict__ a,
                 const float* __restrict__ W,
                 float* __restrict__ out)
{
    __shared__ float invs_sh[AD];
    __shared__ float Wsh[AD * 65];

    const int tid  = threadIdx.x;
    const int lane = tid & 31;
    const int warp = tid >> 5;
    const int row  = blockIdx.x * ROWS_PER_BLOCK + warp;

    // 1/softplus(a_i); a in [0.5,1.5] so no overflow.
    if (tid < AD) {
        invs_sh[tid] = 1.0f / log1pf(__expf(a[tid]));
    }
    __syncthreads();

    // Stage W scaled by -1/softplus(a_row). 4096 floats = 1024 float4.
    const float4* W4 = (const float4*)W;
    #pragma unroll
    for (int k = 0; k < 8; ++k) {
        int idx = tid + NTHREADS * k;   // float4 index; 16 per row
        int r   = idx >> 4;
        int c4  = idx & 15;
        float4 v = W4[idx];
        float  sc = -invs_sh[r];
        float* dst = &Wsh[r * 65 + c4 * 4];
        dst[0] = v.x * sc; dst[1] = v.y * sc; dst[2] = v.z * sc; dst[3] = v.w * sc;
    }
    __syncthreads();

    // Per-lane scaled targets: acc starts at y'_m and accumulates Wsh*t.
    const float* yr = y + row * AD;
    float acc0 = yr[lane]      * invs_sh[lane];
    float acc1 = yr[lane + 32] * invs_sh[lane + 32];
    float out0 = 0.0f, out1 = 0.0f;

    // Chunk 0 partials: dims 0..3 live in acc0 of lanes 0..3.
    float b0 = __shfl_sync(0xffffffffu, acc0, 0);
    float b1 = __shfl_sync(0xffffffffu, acc0, 1);
    float b2 = __shfl_sync(0xffffffffu, acc0, 2);
    float b3 = __shfl_sync(0xffffffffu, acc0, 3);

    #pragma unroll
    for (int c = 0; c < 16; ++c) {
        const int j = 4 * c;

        // ---- dim j ----
        float x0 = b0;                       // b0 already holds all t_{<j}
        float t0 = tanh_fast(x0);
        if (j < 32) out0 = (lane == j)      ? x0 : out0;
        else        out1 = (lane == j - 32) ? x0 : out1;

        // ---- dim j+1 (chain) ----
        float x1 = fmaf(Wsh[(j + 1) * 65 + j], t0, b1);
        float t1 = tanh_fast(x1);
        if (j + 1 < 32) out0 = (lane == j + 1)      ? x1 : out0;
        else            out1 = (lane == j + 1 - 32) ? x1 : out1;

        // acc updates with t0, t1 (rows above/at diagonal are zero => exact).
        acc0 = fmaf(Wsh[lane * 65 + j],            t0, acc0);
        acc1 = fmaf(Wsh[(lane + 32) * 65 + j],     t0, acc1);
        acc0 = fmaf(Wsh[lane * 65 + j + 1],        t1, acc0);
        acc1 = fmaf(Wsh[(lane + 32) * 65 + j + 1], t1, acc1);

        // Early shfl of next chunk's partials (contain t_{<=j+1}); the
        // missing t_{j+2}, t_{j+3} updates are replayed below on all lanes.
        float bp0 = 0.f, bp1 = 0.f, bp2 = 0.f, bp3 = 0.f;
        if (c < 15) {
            float src = (j + 4 < 32) ? acc0 : acc1;
            bp0 = __shfl_sync(0xffffffffu, src, (j + 4) & 31);
            bp1 = __shfl_sync(0xffffffffu, src, (j + 5) & 31);
            bp2 = __shfl_sync(0xffffffffu, src, (j + 6) & 31);
            bp3 = __shfl_sync(0xffffffffu, src, (j + 7) & 31);
        }

        // ---- dim j+2 ----
        float x2 = fmaf(Wsh[(j + 2) * 65 + j + 1], t1,
                   fmaf(Wsh[(j + 2) * 65 + j],     t0, b2));
        float t2 = tanh_fast(x2);
        if (j + 2 < 32) out0 = (lane == j + 2)      ? x2 : out0;
        else            out1 = (lane == j + 2 - 32) ? x2 : out1;

        acc0 = fmaf(Wsh[lane * 65 + j + 2],        t2, acc0);
        acc1 = fmaf(Wsh[(lane + 32) * 65 + j + 2], t2, acc1);

        // ---- dim j+3 ----
        float x3 = fmaf(Wsh[(j + 3) * 65 + j + 2], t2,
                   fmaf(Wsh[(j + 3) * 65 + j + 1], t1,
                   fmaf(Wsh[(j + 3) * 65 + j],     t0, b3)));
        float t3 = tanh_fast(x3);
        if (j + 3 < 32) out0 = (lane == j + 3)      ? x3 : out0;
        else            out1 = (lane == j + 3 - 32) ? x3 : out1;

        acc0 = fmaf(Wsh[lane * 65 + j + 3],        t3, acc0);
        acc1 = fmaf(Wsh[(lane + 32) * 65 + j + 3], t3, acc1);

        // Replay t_{j+2}, t_{j+3} into the early-shfl'd partials -> next b's.
        if (c < 15) {
            b0 = fmaf(Wsh[(j + 4) * 65 + j + 3], t3,
                 fmaf(Wsh[(j + 4) * 65 + j + 2], t2, bp0));
            b1 = fmaf(Wsh[(j + 5) * 65 + j + 3], t3,
                 fmaf(Wsh[(j + 5) * 65 + j + 2], t2, bp1));
            b2 = fmaf(Wsh[(j + 6) * 65 + j + 3], t3,
                 fmaf(Wsh[(j + 6) * 65 + j + 2], t2, bp2));
            b3 = fmaf(Wsh[(j + 7) * 65 + j + 3], t3,
                 fmaf(Wsh[(j + 7) * 65 + j + 2], t2, bp3));
        }
    }

    // Coalesced store.
    out[row * AD + lane]      = out0;
    out[row * AD + lane + 32] = out1;
}

extern "C" void kernel_launch(void* const* d_in, const int* in_sizes, int n_in,
                              void* d_out, int out_size)
{
    const float* y = (const float*)d_in[0];   // (512, 64)
    const float* a = (const float*)d_in[1];   // (64,)
    const float* W = (const float*)d_in[2];   // (64, 64)
    float* out = (float*)d_out;               // (512, 64)

    arbi_kernel<<<AB / ROWS_PER_BLOCK, NTHREADS>>>(y, a, W, out);
}